// round 5
// baseline (speedup 1.0000x reference)
#include <cuda_runtime.h>
#include <cuda_bf16.h>
#include <cstdint>

// Problem constants (fixed by the dataset): input [B, C, T] fp32
#define B_DIM 16
#define C_DIM 256
#define T_DIM 16000
#define TILE_T 256                      // timesteps per block (== blockDim.x)
#define NT ((T_DIM + TILE_T - 1) / TILE_T)   // 63 tiles per batch
#define NTOT (B_DIM * NT)               // 1008 blocks
#define SMEM_C 64                       // channels staged in smem (64KB tile)
#define EPS 1e-8f

// ---- lookback scratch (device globals: no allocation allowed) ----
__device__ int   g_counter;
__device__ int   g_flag[NTOT];          // 0=invalid, 1=aggregate ready, 2=inclusive ready
__device__ float g_aggS[NTOT], g_aggP[NTOT];
__device__ float g_incS[NTOT], g_incP[NTOT];

__global__ void reset_kernel() {
    int i = blockIdx.x * blockDim.x + threadIdx.x;
    if (i == 0) g_counter = 0;
    if (i < NTOT) g_flag[i] = 0;
}

__global__ __launch_bounds__(TILE_T) void cln_kernel(
    const float* __restrict__ x,
    const float* __restrict__ gain,
    const float* __restrict__ bias,
    float* __restrict__ out)
{
    // 64KB dynamic smem: stages channels [0, SMEM_C) of this block's tile.
    // Also serves as occupancy cap: 3 blocks/SM -> L2-retained footprint fits.
    extern __shared__ float s_tile[];   // [SMEM_C][TILE_T]

    __shared__ float ssum[TILE_T];
    __shared__ float spow[TILE_T];
    __shared__ float s_gain[C_DIM];
    __shared__ float s_bias[C_DIM];
    __shared__ float s_exc[2];
    __shared__ int   s_ticket;

    const int tid = threadIdx.x;

    // Dynamic ticket: claim order == atomicAdd order, so all predecessors of a
    // claimed tile are held by blocks already running/finished -> deadlock-free.
    if (tid == 0) s_ticket = atomicAdd(&g_counter, 1);
    s_gain[tid] = gain[tid];
    s_bias[tid] = bias[tid];
    __syncthreads();

    const int r    = s_ticket;
    const int b    = r / NT;
    const int tile = r % NT;
    const int t    = tile * TILE_T + tid;
    const bool valid = (t < T_DIM);

    const float* px = x + (size_t)b * C_DIM * T_DIM + t;

    // ---------- Phase 1: per-t reduction over channels (coalesced) ----------
    float s = 0.f, p = 0.f;
    if (valid) {
        // Channels [0, SMEM_C): streaming loads (L2 evict-first), staged in smem.
        #pragma unroll 8
        for (int c = 0; c < SMEM_C; c++) {
            float v = __ldcs(px + (size_t)c * T_DIM);
            s_tile[c * TILE_T + tid] = v;
            s += v;
            p = fmaf(v, v, p);
        }
        // Channels [SMEM_C, C): default caching — must survive in L2 until phase 2.
        #pragma unroll 8
        for (int c = SMEM_C; c < C_DIM; c++) {
            float v = px[(size_t)c * T_DIM];
            s += v;
            p = fmaf(v, v, p);
        }
    }

    // ---------- Block-wide inclusive scan over t (Hillis-Steele) ----------
    ssum[tid] = s; spow[tid] = p;
    __syncthreads();
    #pragma unroll
    for (int off = 1; off < TILE_T; off <<= 1) {
        float as = 0.f, ap = 0.f;
        if (tid >= off) { as = ssum[tid - off]; ap = spow[tid - off]; }
        __syncthreads();
        if (tid >= off) { ssum[tid] += as; spow[tid] += ap; }
        __syncthreads();
    }
    const float incS = ssum[tid];
    const float incP = spow[tid];
    const float aggS = ssum[TILE_T - 1];   // invalid tail threads contributed 0
    const float aggP = spow[TILE_T - 1];

    // ---------- Decoupled lookback (thread 0) ----------
    if (tid == 0) {
        const int idx = r;
        const int chain_start = b * NT;
        volatile int*   vflag = g_flag;
        volatile float* vaS = g_aggS; volatile float* vaP = g_aggP;
        volatile float* viS = g_incS; volatile float* viP = g_incP;

        float excS = 0.f, excP = 0.f;

        if (tile == 0) {
            // Chain start publishes ONLY inclusive (flag=2): walkers can't pass it.
            viS[idx] = aggS; viP[idx] = aggP;
            __threadfence();
            vflag[idx] = 2;
        } else {
            vaS[idx] = aggS; vaP[idx] = aggP;
            __threadfence();
            vflag[idx] = 1;

            int pred = idx - 1;
            while (true) {
                int f;
                while ((f = vflag[pred]) == 0) { __nanosleep(40); }
                __threadfence();
                if (f == 2) { excS += viS[pred]; excP += viP[pred]; break; }
                excS += vaS[pred]; excP += vaP[pred];
                pred--;
                if (pred < chain_start) break;   // defensive; unreachable
            }
            viS[idx] = excS + aggS; viP[idx] = excP + aggP;
            __threadfence();
            vflag[idx] = 2;
        }

        s_exc[0] = excS; s_exc[1] = excP;
    }
    __syncthreads();

    // ---------- Phase 2: normalize; staged channels from smem, rest from L2 ----------
    if (valid) {
        const float cumS = s_exc[0] + incS;
        const float cumP = s_exc[1] + incP;
        const float cnt  = (float)(t + 1) * (float)C_DIM;
        const float mean = cumS / cnt;
        const float var  = cumP / cnt - mean * mean;
        const float inv  = rsqrtf(var + EPS);

        float* po = out + (size_t)b * C_DIM * T_DIM + t;
        #pragma unroll 8
        for (int c = 0; c < SMEM_C; c++) {
            float v = s_tile[c * TILE_T + tid];
            __stcs(po + (size_t)c * T_DIM,
                   fmaf((v - mean) * inv, s_gain[c], s_bias[c]));
        }
        #pragma unroll 8
        for (int c = SMEM_C; c < C_DIM; c++) {
            float v = __ldlu(px + (size_t)c * T_DIM);   // last-use: free the L2 line
            __stcs(po + (size_t)c * T_DIM,
                   fmaf((v - mean) * inv, s_gain[c], s_bias[c]));
        }
    }
}

extern "C" void kernel_launch(void* const* d_in, const int* in_sizes, int n_in,
                              void* d_out, int out_size)
{
    const float* x    = (const float*)d_in[0];
    const float* gain = (const float*)d_in[1];
    const float* bias = (const float*)d_in[2];
    float* out = (float*)d_out;

    const int smem_bytes = SMEM_C * TILE_T * sizeof(float);   // 64KB
    cudaFuncSetAttribute(cln_kernel, cudaFuncAttributeMaxDynamicSharedMemorySize,
                         smem_bytes);

    reset_kernel<<<(NTOT + 255) / 256, 256>>>();
    cln_kernel<<<NTOT, TILE_T, smem_bytes>>>(x, gain, bias, out);
}

// round 6
// speedup vs baseline: 1.8972x; 1.8972x over previous
#include <cuda_runtime.h>
#include <cuda_bf16.h>
#include <cstdint>

// Problem constants (fixed by the dataset): input [B, C, T] fp32
#define B_DIM 16
#define C_DIM 256
#define T_DIM 16000
#define EPS 1e-8f

#define K1_TPB 256
#define T_PER_BLK 1024                 // K1/K3: 256 threads x 4 t (float4)
#define NCHUNK ((T_DIM + T_PER_BLK - 1) / T_PER_BLK)   // 16 (last chunk: 640 t = 160 thr)

// scratch (device globals; allocation is forbidden)
__device__ float2 g_colsum[B_DIM * T_DIM];   // (sum, sumsq) per (b,t)   2 MB
__device__ float2 g_stats [B_DIM * T_DIM];   // (mean, inv_std) per (b,t) 2 MB

// ---------------- K1: per-timestep channel reduction (pure streaming) ----------------
__global__ __launch_bounds__(K1_TPB) void colsum_kernel(const float* __restrict__ x)
{
    const int b  = blockIdx.y;
    const int t4 = blockIdx.x * T_PER_BLK + threadIdx.x * 4;
    if (t4 >= T_DIM) return;                          // whole thread valid or not (640%4==0)

    const float* px = x + (size_t)b * C_DIM * T_DIM + t4;

    float4 s = make_float4(0.f, 0.f, 0.f, 0.f);
    float4 p = make_float4(0.f, 0.f, 0.f, 0.f);
    #pragma unroll 8
    for (int c = 0; c < C_DIM; c++) {
        const float4 v = __ldcs((const float4*)(px + (size_t)c * T_DIM));
        s.x += v.x; s.y += v.y; s.z += v.z; s.w += v.w;
        p.x = fmaf(v.x, v.x, p.x); p.y = fmaf(v.y, v.y, p.y);
        p.z = fmaf(v.z, v.z, p.z); p.w = fmaf(v.w, v.w, p.w);
    }

    float2* dst = g_colsum + (size_t)b * T_DIM + t4;
    // two 16B stores: {s0,p0,s1,p1} {s2,p2,s3,p3}
    ((float4*)dst)[0] = make_float4(s.x, p.x, s.y, p.y);
    ((float4*)dst)[1] = make_float4(s.z, p.z, s.w, p.w);
}

// ---------------- K2: per-batch inclusive scan -> (mean, inv_std) ----------------
#define SCAN_TPB 1024
#define EPT 16                                        // elements per thread (1024*16 >= 16000)

__global__ __launch_bounds__(SCAN_TPB) void scan_kernel()
{
    __shared__ float swS[32], swP[32];

    const int b    = blockIdx.x;
    const int tid  = threadIdx.x;
    const int lane = tid & 31;
    const int wid  = tid >> 5;
    const size_t base = (size_t)b * T_DIM;
    const int start = tid * EPT;

    // load EPT consecutive (sum,pow) pairs and local inclusive scan
    float vs[EPT], vp[EPT];
    #pragma unroll
    for (int j = 0; j < EPT; j++) {
        const int i = start + j;
        float2 v = (i < T_DIM) ? g_colsum[base + i] : make_float2(0.f, 0.f);
        vs[j] = v.x; vp[j] = v.y;
    }
    #pragma unroll
    for (int j = 1; j < EPT; j++) { vs[j] += vs[j - 1]; vp[j] += vp[j - 1]; }

    // block-exclusive prefix of thread totals
    float tS = vs[EPT - 1], tP = vp[EPT - 1];
    float iS = tS, iP = tP;                       // warp-inclusive
    #pragma unroll
    for (int off = 1; off < 32; off <<= 1) {
        float nS = __shfl_up_sync(0xffffffffu, iS, off);
        float nP = __shfl_up_sync(0xffffffffu, iP, off);
        if (lane >= off) { iS += nS; iP += nP; }
    }
    if (lane == 31) { swS[wid] = iS; swP[wid] = iP; }
    __syncthreads();
    if (wid == 0) {
        float wS = swS[lane], wP = swP[lane];
        #pragma unroll
        for (int off = 1; off < 32; off <<= 1) {
            float nS = __shfl_up_sync(0xffffffffu, wS, off);
            float nP = __shfl_up_sync(0xffffffffu, wP, off);
            if (lane >= off) { wS += nS; wP += nP; }
        }
        swS[lane] = wS - swS[lane];               // exclusive warp offset
        swP[lane] = wP - swP[lane];
    }
    __syncthreads();
    const float excS = swS[wid] + (iS - tS);      // thread-exclusive prefix
    const float excP = swP[wid] + (iP - tP);

    #pragma unroll
    for (int j = 0; j < EPT; j++) {
        const int i = start + j;
        if (i < T_DIM) {
            const float cumS = excS + vs[j];
            const float cumP = excP + vp[j];
            const float cnt  = (float)(i + 1) * (float)C_DIM;
            const float mean = cumS / cnt;
            const float inv  = rsqrtf(cumP / cnt - mean * mean + EPS);
            g_stats[base + i] = make_float2(mean, inv);
        }
    }
}

// ---------------- K3: normalize (pure streaming; stats hit L2) ----------------
__global__ __launch_bounds__(K1_TPB) void norm_kernel(
    const float* __restrict__ x,
    const float* __restrict__ gain,
    const float* __restrict__ bias,
    float* __restrict__ out)
{
    const int c  = blockIdx.y;
    const int b  = blockIdx.z;
    const int t4 = blockIdx.x * T_PER_BLK + threadIdx.x * 4;
    if (t4 >= T_DIM) return;

    const size_t off = ((size_t)b * C_DIM + c) * T_DIM + t4;
    const float4 v = __ldcs((const float4*)(x + off));

    const float4* sp = (const float4*)(g_stats + (size_t)b * T_DIM + t4);
    const float4 s01 = sp[0];     // {mean0, inv0, mean1, inv1}
    const float4 s23 = sp[1];

    const float g  = __ldg(gain + c);
    const float bi = __ldg(bias + c);

    float4 o;
    o.x = fmaf((v.x - s01.x) * s01.y, g, bi);
    o.y = fmaf((v.y - s01.z) * s01.w, g, bi);
    o.z = fmaf((v.z - s23.x) * s23.y, g, bi);
    o.w = fmaf((v.w - s23.z) * s23.w, g, bi);
    __stcs((float4*)(out + off), o);
}

extern "C" void kernel_launch(void* const* d_in, const int* in_sizes, int n_in,
                              void* d_out, int out_size)
{
    const float* x    = (const float*)d_in[0];
    const float* gain = (const float*)d_in[1];
    const float* bias = (const float*)d_in[2];
    float* out = (float*)d_out;

    colsum_kernel<<<dim3(NCHUNK, B_DIM), K1_TPB>>>(x);
    scan_kernel  <<<B_DIM, SCAN_TPB>>>();
    norm_kernel  <<<dim3(NCHUNK, C_DIM, B_DIM), K1_TPB>>>(x, gain, bias, out);
}